// round 6
// baseline (speedup 1.0000x reference)
#include <cuda_runtime.h>
#include <cstddef>

// Problem constants (fixed by setup_inputs)
#define BATCH 1024
#define F1 10          // layer-1 fanout
#define F0 25          // layer-0 fanout
#define D 128          // feature dim
#define NROWS1 (BATCH*F1)        // 10240
#define NTOT (BATCH + NROWS1)    // 11264
#define RT 16                    // rows per layer-0 block

// Scratch (device globals — no allocations allowed).
__device__ float g_N[(size_t)NTOT * 256];

// ---------------------------------------------------------------------------
// Gather helper: warp-cooperative. Each warp produces the self row and the
// neighbor-mean row for rows (warp, warp+8) of the block tile.
// CNT is the fanout (compile-time so the loop fully unrolls -> MLP).
// ---------------------------------------------------------------------------
template<int CNT>
__device__ __forceinline__ void gather_rows(
    const float* __restrict__ features, const int* __restrict__ adj,
    const int* __restrict__ selfIdx, float (*Xs)[D], float (*Xn)[D],
    int warp, int lane)
{
    #pragma unroll
    for (int rr = warp; rr < RT; rr += 8) {
        int s = selfIdx[rr];
        const float4* frow = (const float4*)(features + (size_t)s * D);
        ((float4*)Xs[rr])[lane] = frow[lane];

        const int* arow = adj + (size_t)s * 128;
        float4 acc = make_float4(0.f, 0.f, 0.f, 0.f);
        #pragma unroll
        for (int j = 0; j < CNT; j++) {
            int nb = __ldg(arow + j);
            float4 nv = ((const float4*)(features + (size_t)nb * D))[lane];
            acc.x += nv.x; acc.y += nv.y; acc.z += nv.z; acc.w += nv.w;
        }
        const float inv = 1.f / CNT;
        acc.x *= inv; acc.y *= inv; acc.z *= inv; acc.w *= inv;
        ((float4*)Xn[rr])[lane] = acc;
    }
}

// ---------------------------------------------------------------------------
// K_A: fused sample + aggregate + layer-0 GEMM (+ReLU).
// grid = NTOT/RT = 704 blocks x 256 threads. Block handles 16 rows x 256 cols.
// Blocks [0,64) are level-0 rows (fanout 10); [64,704) level-1 (fanout 25).
// Gather phase (mem-bound) and GEMM phase (FMA-bound) overlap across blocks.
// ---------------------------------------------------------------------------
__global__ void __launch_bounds__(256)
k_layer0(const float* __restrict__ features, const int* __restrict__ adj,
         const int* __restrict__ batch,
         const float* __restrict__ ws0, const float* __restrict__ wn0)
{
    __shared__ __align__(16) float Xs[RT][D];    // self rows        8 KB
    __shared__ __align__(16) float Xn[RT][D];    // neighbor means   8 KB
    __shared__ float Wc[16][256];                // W k-chunk       16 KB
    __shared__ int   selfIdx[RT];

    const int tid  = threadIdx.x;
    const int warp = tid >> 5, lane = tid & 31;
    const int r0   = blockIdx.x * RT;

    // Row "self" indices (16 threads, <=2 dependent loads each)
    if (tid < RT) {
        int r = r0 + tid;
        int s;
        if (r < BATCH) {
            s = batch[r];
        } else {
            int i = r - BATCH;
            s = adj[(size_t)batch[i / F1] * 128 + (i % F1)];
        }
        selfIdx[tid] = s;
    }
    __syncthreads();

    // Gather phase (whole block is one level -> compile-time fanout)
    if (r0 < BATCH)
        gather_rows<F1>(features, adj, selfIdx, Xs, Xn, warp, lane);
    else
        gather_rows<F0>(features, adj, selfIdx, Xs, Xn, warp, lane);

    // GEMM phase: thread owns output column tid for all 16 rows.
    // cols [0,128): relu(Xs @ ws0); cols [128,256): relu(Xn @ wn0)
    float acc[RT];
    #pragma unroll
    for (int r = 0; r < RT; r++) acc[r] = 0.f;

    const float4* X4 = (const float4*)((tid < 128) ? &Xs[0][0] : &Xn[0][0]);

    #pragma unroll
    for (int kc = 0; kc < D; kc += 16) {
        __syncthreads();   // Wc reuse guard (also orders gather before 1st read)
        #pragma unroll
        for (int i = tid; i < 16 * 256; i += 256) {
            int kk = i >> 8, cc = i & 255;
            Wc[kk][cc] = (cc < 128 ? ws0 : wn0)[(size_t)(kc + kk) * 128 + (cc & 127)];
        }
        __syncthreads();

        #pragma unroll
        for (int k4 = 0; k4 < 4; k4++) {
            float w0 = Wc[k4 * 4 + 0][tid];
            float w1 = Wc[k4 * 4 + 1][tid];
            float w2 = Wc[k4 * 4 + 2][tid];
            float w3 = Wc[k4 * 4 + 3][tid];
            #pragma unroll
            for (int r = 0; r < RT; r++) {
                float4 xv = X4[r * (D / 4) + (kc >> 2) + k4];   // broadcast LDS
                float a = acc[r];
                a = fmaf(xv.x, w0, a);
                a = fmaf(xv.y, w1, a);
                a = fmaf(xv.z, w2, a);
                a = fmaf(xv.w, w3, a);
                acc[r] = a;
            }
        }
    }

    #pragma unroll
    for (int r = 0; r < RT; r++)
        g_N[(size_t)(r0 + r) * 256 + tid] = fmaxf(acc[r], 0.f);
}

// ---------------------------------------------------------------------------
// K_B: fused tail: mean-of-10 + layer-1 GEMM (identity) + l2-normalize + pred.
// grid = 128 blocks x 256 threads; 8 batch rows per block.
// ---------------------------------------------------------------------------
__global__ void __launch_bounds__(256)
k_tail(const float* __restrict__ ws1, const float* __restrict__ wn1,
       const float* __restrict__ wp, float* __restrict__ out)
{
    __shared__ __align__(16) float Ns[8][256];   // n0 rows     8 KB
    __shared__ __align__(16) float Ms[8][256];   // m1 rows     8 KB
    __shared__ float Wc[16][256];                // W chunk    16 KB
    __shared__ float Ys[8][256];                 // y rows      8 KB
    __shared__ float inv[8];

    const int tid = threadIdx.x;
    const int r0  = blockIdx.x * 8;

    // n0 rows (first 1024 rows of g_N)
    #pragma unroll
    for (int i = tid; i < 8 * 256; i += 256)
        (&Ns[0][0])[i] = g_N[(size_t)r0 * 256 + i];

    // m1 rows: mean over 10 consecutive n1 rows
    #pragma unroll
    for (int rr = 0; rr < 8; rr++) {
        const float* base = g_N + (size_t)(BATCH + (r0 + rr) * F1) * 256 + tid;
        float s = 0.f;
        #pragma unroll
        for (int j = 0; j < F1; j++)
            s += base[(size_t)j * 256];
        Ms[rr][tid] = s * (1.f / F1);
    }

    // Layer-1 GEMM: K=256, thread owns col tid for 8 rows.
    float acc[8];
    #pragma unroll
    for (int r = 0; r < 8; r++) acc[r] = 0.f;
    const float4* X4 = (const float4*)((tid < 128) ? &Ns[0][0] : &Ms[0][0]);

    #pragma unroll
    for (int kc = 0; kc < 256; kc += 16) {
        __syncthreads();
        #pragma unroll
        for (int i = tid; i < 16 * 256; i += 256) {
            int kk = i >> 8, cc = i & 255;
            Wc[kk][cc] = (cc < 128 ? ws1 : wn1)[(size_t)(kc + kk) * 128 + (cc & 127)];
        }
        __syncthreads();

        #pragma unroll
        for (int k4 = 0; k4 < 4; k4++) {
            float w0 = Wc[k4 * 4 + 0][tid];
            float w1 = Wc[k4 * 4 + 1][tid];
            float w2 = Wc[k4 * 4 + 2][tid];
            float w3 = Wc[k4 * 4 + 3][tid];
            #pragma unroll
            for (int r = 0; r < 8; r++) {
                float4 xv = X4[r * 64 + (kc >> 2) + k4];
                float a = acc[r];
                a = fmaf(xv.x, w0, a);
                a = fmaf(xv.y, w1, a);
                a = fmaf(xv.z, w2, a);
                a = fmaf(xv.w, w3, a);
                acc[r] = a;
            }
        }
    }
    __syncthreads();
    #pragma unroll
    for (int r = 0; r < 8; r++)
        Ys[r][tid] = acc[r];
    __syncthreads();

    // Per-row inverse L2 norm (8 rows x 32 lanes)
    {
        int row = tid >> 5, lane = tid & 31;
        float s = 0.f;
        #pragma unroll
        for (int k = lane; k < 256; k += 32) {
            float v = Ys[row][k];
            s += v * v;
        }
        #pragma unroll
        for (int o = 16; o > 0; o >>= 1)
            s += __shfl_xor_sync(0xFFFFFFFFu, s, o);
        if (lane == 0)
            inv[row] = rsqrtf(fmaxf(s, 1e-12f));
    }
    __syncthreads();

    // Pred head [256 -> 50], normalization folded as output scale.
    const int c  = tid & 63;
    const int rg = tid >> 6;
    if (c < 50) {
        const int rl = rg * 2;
        float a0 = 0.f, a1 = 0.f;
        #pragma unroll 4
        for (int k = 0; k < 256; k++) {
            float w = wp[k * 50 + c];
            a0 = fmaf(Ys[rl][k], w, a0);
            a1 = fmaf(Ys[rl + 1][k], w, a1);
        }
        out[(size_t)(r0 + rl) * 50 + c]     = a0 * inv[rl];
        out[(size_t)(r0 + rl + 1) * 50 + c] = a1 * inv[rl + 1];
    }
}

// ---------------------------------------------------------------------------
extern "C" void kernel_launch(void* const* d_in, const int* in_sizes, int n_in,
                              void* d_out, int out_size)
{
    const float* features = (const float*)d_in[0];
    const int*   adj      = (const int*)d_in[1];
    const int*   batch    = (const int*)d_in[2];   // int32 (JAX x64 disabled)
    const float* ws0      = (const float*)d_in[3];
    const float* wn0      = (const float*)d_in[4];
    const float* ws1      = (const float*)d_in[5];
    const float* wn1      = (const float*)d_in[6];
    const float* wp       = (const float*)d_in[7];
    float*       out      = (float*)d_out;

    k_layer0<<<NTOT / RT, 256>>>(features, adj, batch, ws0, wn0);
    k_tail<<<BATCH / 8, 256>>>(ws1, wn1, wp, out);
}

// round 7
// speedup vs baseline: 1.2495x; 1.2495x over previous
#include <cuda_runtime.h>
#include <cstddef>

// Problem constants (fixed by setup_inputs)
#define BATCH 1024
#define F1 10          // layer-1 fanout
#define F0 25          // layer-0 fanout
#define D 128          // feature dim
#define NROWS1 (BATCH*F1)        // 10240
#define NTOT (BATCH + NROWS1)    // 11264
#define RT 32                    // rows per layer-0 block (NTOT/RT = 352)

// Scratch (device globals — no allocations allowed).
__device__ float g_N[(size_t)NTOT * 256];

// ---------------------------------------------------------------------------
// Gather helper: warp-cooperative. Each warp produces self row + neighbor-mean
// row for rows warp, warp+8, warp+16, warp+24 of the block tile.
// CNT compile-time -> fully unrolled j-loop -> MLP ~25.
// ---------------------------------------------------------------------------
template<int CNT>
__device__ __forceinline__ void gather_rows(
    const float* __restrict__ features, const int* __restrict__ adj,
    const int* __restrict__ selfIdx, float (*Xs)[D], float (*Xn)[D],
    int warp, int lane)
{
    #pragma unroll
    for (int rr = warp; rr < RT; rr += 8) {
        int s = selfIdx[rr];
        ((float4*)Xs[rr])[lane] = ((const float4*)(features + (size_t)s * D))[lane];

        const int* arow = adj + (size_t)s * 128;
        float4 acc = make_float4(0.f, 0.f, 0.f, 0.f);
        #pragma unroll
        for (int j = 0; j < CNT; j++) {
            int nb = __ldg(arow + j);
            float4 nv = ((const float4*)(features + (size_t)nb * D))[lane];
            acc.x += nv.x; acc.y += nv.y; acc.z += nv.z; acc.w += nv.w;
        }
        const float inv = 1.f / CNT;
        acc.x *= inv; acc.y *= inv; acc.z *= inv; acc.w *= inv;
        ((float4*)Xn[rr])[lane] = acc;
    }
}

// ---------------------------------------------------------------------------
// K_A: fused sample + aggregate + layer-0 GEMM (+ReLU).
// grid = 352 blocks x 256 threads; block = 32 rows x 256 cols.
// Blocks [0,32) are level-0 rows (fanout 10); [32,352) level-1 (fanout 25).
// W streamed from L2 into registers (no smem W, no k-loop barriers).
// ---------------------------------------------------------------------------
__global__ void __launch_bounds__(256)
k_layer0(const float* __restrict__ features, const int* __restrict__ adj,
         const int* __restrict__ batch,
         const float* __restrict__ ws0, const float* __restrict__ wn0)
{
    __shared__ __align__(16) float Xs[RT][D];    // self rows       16 KB
    __shared__ __align__(16) float Xn[RT][D];    // neighbor means  16 KB
    __shared__ int   selfIdx[RT];

    const int tid  = threadIdx.x;
    const int warp = tid >> 5, lane = tid & 31;
    const int r0   = blockIdx.x * RT;

    // Row "self" indices
    if (tid < RT) {
        int r = r0 + tid;
        int s;
        if (r < BATCH) {
            s = batch[r];
        } else {
            int i = r - BATCH;
            s = adj[(size_t)batch[i / F1] * 128 + (i % F1)];
        }
        selfIdx[tid] = s;
    }
    __syncthreads();

    // Gather (whole block is one level -> compile-time fanout)
    if (r0 < BATCH)
        gather_rows<F1>(features, adj, selfIdx, Xs, Xn, warp, lane);
    else
        gather_rows<F0>(features, adj, selfIdx, Xs, Xn, warp, lane);
    __syncthreads();

    // GEMM: thread owns output column tid for all 32 rows.
    // cols [0,128): relu(Xs @ ws0); cols [128,256): relu(Xn @ wn0)
    float acc[RT];
    #pragma unroll
    for (int r = 0; r < RT; r++) acc[r] = 0.f;

    const float4* X4   = (const float4*)((tid < 128) ? &Xs[0][0] : &Xn[0][0]);
    const float*  wcol = ((tid < 128) ? ws0 : wn0) + (tid & 127);

    #pragma unroll 4
    for (int k8 = 0; k8 < D / 8; k8++) {
        float w[8];
        #pragma unroll
        for (int j = 0; j < 8; j++)
            w[j] = __ldg(wcol + (size_t)(k8 * 8 + j) * 128);
        #pragma unroll
        for (int h = 0; h < 2; h++) {
            #pragma unroll
            for (int r = 0; r < RT; r++) {
                float4 xv = X4[r * (D / 4) + k8 * 2 + h];   // broadcast LDS
                float a = acc[r];
                a = fmaf(xv.x, w[h * 4 + 0], a);
                a = fmaf(xv.y, w[h * 4 + 1], a);
                a = fmaf(xv.z, w[h * 4 + 2], a);
                a = fmaf(xv.w, w[h * 4 + 3], a);
                acc[r] = a;
            }
        }
    }

    #pragma unroll
    for (int r = 0; r < RT; r++)
        g_N[(size_t)(r0 + r) * 256 + tid] = fmaxf(acc[r], 0.f);
}

// ---------------------------------------------------------------------------
// K_B: fused tail: mean-of-10 + layer-1 GEMM + l2-normalize + pred.
// grid = 256 blocks x 256 threads; 4 batch rows per block (full 256-col width
// per block so norm+pred stay in-block). W streamed from L2, no k-barriers.
// ---------------------------------------------------------------------------
__global__ void __launch_bounds__(256)
k_tail(const float* __restrict__ ws1, const float* __restrict__ wn1,
       const float* __restrict__ wp, float* __restrict__ out)
{
    __shared__ __align__(16) float Ns[4][256];   // n0 rows   4 KB
    __shared__ __align__(16) float Ms[4][256];   // m1 rows   4 KB
    __shared__ float Ys[4][256];                 // y rows    4 KB
    __shared__ float inv4[4];

    const int tid = threadIdx.x;
    const int r0  = blockIdx.x * 4;

    // n0 rows (first 1024 rows of g_N)
    #pragma unroll
    for (int rr = 0; rr < 4; rr++)
        Ns[rr][tid] = g_N[(size_t)(r0 + rr) * 256 + tid];

    // m1 rows: mean over 10 consecutive n1 rows
    #pragma unroll
    for (int rr = 0; rr < 4; rr++) {
        const float* base = g_N + (size_t)(BATCH + (r0 + rr) * F1) * 256 + tid;
        float s = 0.f;
        #pragma unroll
        for (int j = 0; j < F1; j++)
            s += base[(size_t)j * 256];
        Ms[rr][tid] = s * (1.f / F1);
    }
    __syncthreads();

    // Layer-1 GEMM: K=256, thread owns col tid for 4 rows.
    float acc[4] = {0.f, 0.f, 0.f, 0.f};
    const float4* X4   = (const float4*)((tid < 128) ? &Ns[0][0] : &Ms[0][0]);
    const float*  wcol = ((tid < 128) ? ws1 : wn1) + (tid & 127);

    #pragma unroll 4
    for (int k8 = 0; k8 < 256 / 8; k8++) {
        float w[8];
        #pragma unroll
        for (int j = 0; j < 8; j++)
            w[j] = __ldg(wcol + (size_t)(k8 * 8 + j) * 128);
        #pragma unroll
        for (int h = 0; h < 2; h++) {
            #pragma unroll
            for (int r = 0; r < 4; r++) {
                float4 xv = X4[r * 64 + k8 * 2 + h];
                float a = acc[r];
                a = fmaf(xv.x, w[h * 4 + 0], a);
                a = fmaf(xv.y, w[h * 4 + 1], a);
                a = fmaf(xv.z, w[h * 4 + 2], a);
                a = fmaf(xv.w, w[h * 4 + 3], a);
                acc[r] = a;
            }
        }
    }

    #pragma unroll
    for (int r = 0; r < 4; r++)
        Ys[r][tid] = acc[r];
    __syncthreads();

    // Per-row inverse L2 norm: warp w (0..3) reduces row w
    const int warp = tid >> 5, lane = tid & 31;
    if (warp < 4) {
        float s = 0.f;
        #pragma unroll
        for (int k = lane; k < 256; k += 32) {
            float v = Ys[warp][k];
            s += v * v;
        }
        #pragma unroll
        for (int o = 16; o > 0; o >>= 1)
            s += __shfl_xor_sync(0xFFFFFFFFu, s, o);
        if (lane == 0)
            inv4[warp] = rsqrtf(fmaxf(s, 1e-12f));
    }
    __syncthreads();

    // Pred head [256 -> 50], normalization folded as output scale.
    const int c  = tid & 63;
    const int rg = tid >> 6;     // one row per 64-thread group
    if (c < 50) {
        float a = 0.f;
        #pragma unroll 8
        for (int k = 0; k < 256; k++)
            a = fmaf(Ys[rg][k], __ldg(wp + (size_t)k * 50 + c), a);
        out[(size_t)(r0 + rg) * 50 + c] = a * inv4[rg];
    }
}

// ---------------------------------------------------------------------------
extern "C" void kernel_launch(void* const* d_in, const int* in_sizes, int n_in,
                              void* d_out, int out_size)
{
    const float* features = (const float*)d_in[0];
    const int*   adj      = (const int*)d_in[1];
    const int*   batch    = (const int*)d_in[2];   // int32 (JAX x64 disabled)
    const float* ws0      = (const float*)d_in[3];
    const float* wn0      = (const float*)d_in[4];
    const float* ws1      = (const float*)d_in[5];
    const float* wn1      = (const float*)d_in[6];
    const float* wp       = (const float*)d_in[7];
    float*       out      = (float*)d_out;

    k_layer0<<<NTOT / RT, 256>>>(features, adj, batch, ws0, wn0);
    k_tail<<<BATCH / 4, 256>>>(ws1, wn1, wp, out);
}